// round 1
// baseline (speedup 1.0000x reference)
#include <cuda_runtime.h>
#include <cuda_bf16.h>
#include <cfloat>
#include <math.h>

// ---------------------------------------------------------------------------
// Problem constants (fixed by the reference)
// ---------------------------------------------------------------------------
#define BATCH 16
#define NMAX  1024
#define EMAX  16384
#define DIM   512
// layer input sizes and top-k sizes
// ns = {1024, 820, 656}, ks = {820, 656, 525}

// ---------------------------------------------------------------------------
// Device scratch (static allocation; no cudaMalloc allowed)
// ---------------------------------------------------------------------------
__device__ float d_xb [BATCH * NMAX * DIM];        // current node features (32 MB)
__device__ float d_hb [BATCH * NMAX * DIM];        // h / x_new scratch    (32 MB)
__device__ float d_cat[BATCH * NMAX * 2 * DIM];    // [agg | x] concat     (64 MB)

__device__ int   d_srcA[BATCH * EMAX];
__device__ int   d_dstA[BATCH * EMAX];
__device__ int   d_srcB[BATCH * EMAX];
__device__ int   d_dstB[BATCH * EMAX];

__device__ int   d_cnt [BATCH * NMAX];
__device__ int   d_off [BATCH * (NMAX + 1)];
__device__ int   d_cur [BATCH * NMAX];
__device__ int   d_csr [BATCH * EMAX];

__device__ float d_score[BATCH * NMAX];
__device__ int   d_perm [BATCH * NMAX];
__device__ float d_tanhv[BATCH * NMAX];
__device__ int   d_newidx[BATCH * NMAX];

__device__ float d_z[BATCH * 2 * DIM];             // readout accumulator
__device__ float d_norms[4];                       // 1/||pool_w[l]||

__device__ __forceinline__ const int* esrc(int sel) { return sel ? d_srcB : d_srcA; }
__device__ __forceinline__ const int* edst(int sel) { return sel ? d_dstB : d_dstA; }
__device__ __forceinline__ int* esrc_w(int sel) { return sel ? d_srcB : d_srcA; }
__device__ __forceinline__ int* edst_w(int sel) { return sel ? d_dstB : d_dstA; }

// ---------------------------------------------------------------------------
// Init kernels
// ---------------------------------------------------------------------------
__global__ void copy_x_kernel(const float* __restrict__ x) {
    size_t i = (size_t)blockIdx.x * blockDim.x + threadIdx.x;
    size_t total = (size_t)BATCH * NMAX * DIM;
    if (i < total) d_xb[i] = x[i];
}

__global__ void init_edges_kernel(const int* __restrict__ ei) {
    int b = blockIdx.y;
    int e = blockIdx.x * blockDim.x + threadIdx.x;
    if (e < EMAX) {
        d_srcA[b * EMAX + e] = ei[(size_t)b * 2 * EMAX + e];
        d_dstA[b * EMAX + e] = ei[(size_t)b * 2 * EMAX + EMAX + e];
    }
}

__global__ void norms_kernel(const float* __restrict__ pw) {
    int l = blockIdx.x;
    int t = threadIdx.x;  // 256
    __shared__ float red[256];
    float s = 0.f;
    for (int j = t; j < DIM; j += 256) {
        float v = pw[l * DIM + j];
        s = fmaf(v, v, s);
    }
    red[t] = s;
    __syncthreads();
    for (int o = 128; o > 0; o >>= 1) {
        if (t < o) red[t] += red[t + o];
        __syncthreads();
    }
    if (t == 0) d_norms[l] = 1.0f / sqrtf(red[0]);
}

// ---------------------------------------------------------------------------
// GEMM  C[M,N] = act(A[M,K] @ W[N,K]^T + bias)   (NT, both row-major)
// asel: 0 -> A = d_xb (ld 512), 1 -> A = d_cat (ld 1024). C = d_hb (ld 512).
// 128x128 block tile, BK=8, 8x8 per thread, 256 threads.
// ---------------------------------------------------------------------------
__global__ void __launch_bounds__(256) gemm_nt_kernel(
    int asel,
    const float* __restrict__ W,
    const float* __restrict__ bias,   // may be nullptr
    int M, int N, int K, int doRelu)
{
    const int b = blockIdx.z;
    const float* A = asel ? (d_cat + (size_t)b * NMAX * 2 * DIM)
                          : (d_xb  + (size_t)b * NMAX * DIM);
    float* C = d_hb + (size_t)b * NMAX * DIM;

    __shared__ float As[8][128];
    __shared__ float Bs[8][128];

    const int tid  = threadIdx.x;
    const int brow = blockIdx.y * 128;
    const int bcol = blockIdx.x * 128;
    const int tr   = (tid / 16) * 8;
    const int tc   = (tid % 16) * 8;

    float acc[8][8];
#pragma unroll
    for (int i = 0; i < 8; i++)
#pragma unroll
        for (int j = 0; j < 8; j++) acc[i][j] = 0.f;

    const int lr = tid >> 1;        // 0..127
    const int lc = (tid & 1) * 4;   // 0 / 4

    const bool arow_ok = (brow + lr) < M;
    const float* Aload = A + (size_t)(brow + lr) * K + lc;
    const float* Wload = W + (size_t)(bcol + lr) * K + lc;  // N multiple of 128

    for (int k0 = 0; k0 < K; k0 += 8) {
        float4 av = make_float4(0.f, 0.f, 0.f, 0.f);
        if (arow_ok) av = *(const float4*)(Aload + k0);
        float4 wv = *(const float4*)(Wload + k0);
        As[lc + 0][lr] = av.x; As[lc + 1][lr] = av.y;
        As[lc + 2][lr] = av.z; As[lc + 3][lr] = av.w;
        Bs[lc + 0][lr] = wv.x; Bs[lc + 1][lr] = wv.y;
        Bs[lc + 2][lr] = wv.z; Bs[lc + 3][lr] = wv.w;
        __syncthreads();
#pragma unroll
        for (int kk = 0; kk < 8; kk++) {
            float a[8], w8[8];
#pragma unroll
            for (int i = 0; i < 8; i++) a[i] = As[kk][tr + i];
#pragma unroll
            for (int j = 0; j < 8; j++) w8[j] = Bs[kk][tc + j];
#pragma unroll
            for (int i = 0; i < 8; i++)
#pragma unroll
                for (int j = 0; j < 8; j++)
                    acc[i][j] = fmaf(a[i], w8[j], acc[i][j]);
        }
        __syncthreads();
    }

#pragma unroll
    for (int i = 0; i < 8; i++) {
        int r = brow + tr + i;
        if (r < M) {
#pragma unroll
            for (int j = 0; j < 8; j++) {
                int c = bcol + tc + j;
                float v = acc[i][j];
                if (bias) v += bias[c];
                if (doRelu) v = fmaxf(v, 0.f);
                C[(size_t)r * N + c] = v;
            }
        }
    }
}

// ---------------------------------------------------------------------------
// CSR build
// ---------------------------------------------------------------------------
__global__ void zero_cnt_kernel() {
    int i = blockIdx.x * blockDim.x + threadIdx.x;
    if (i < BATCH * NMAX) d_cnt[i] = 0;
}

__global__ void count_kernel(int sel) {
    int b = blockIdx.y;
    int e = blockIdx.x * blockDim.x + threadIdx.x;
    if (e >= EMAX) return;
    int s = esrc(sel)[b * EMAX + e];
    int d = edst(sel)[b * EMAX + e];
    if (s >= 0 && s != d) atomicAdd(&d_cnt[b * NMAX + d], 1);
}

__global__ void __launch_bounds__(1024) scan_kernel(int n) {
    __shared__ int sh[NMAX];
    int b = blockIdx.x, t = threadIdx.x;
    int v = (t < n) ? d_cnt[b * NMAX + t] : 0;
    sh[t] = v;
    __syncthreads();
    for (int off = 1; off < NMAX; off <<= 1) {
        int add = (t >= off) ? sh[t - off] : 0;
        __syncthreads();
        sh[t] += add;
        __syncthreads();
    }
    int excl = sh[t] - v;
    d_off[b * (NMAX + 1) + t] = excl;
    d_cur[b * NMAX + t]       = excl;
    if (t == NMAX - 1) d_off[b * (NMAX + 1) + NMAX] = sh[t];
    if (t == n - 1)    d_off[b * (NMAX + 1) + n]    = sh[t];
}

__global__ void fill_kernel(int sel) {
    int b = blockIdx.y;
    int e = blockIdx.x * blockDim.x + threadIdx.x;
    if (e >= EMAX) return;
    int s = esrc(sel)[b * EMAX + e];
    int d = edst(sel)[b * EMAX + e];
    if (s >= 0 && s != d) {
        int pos = atomicAdd(&d_cur[b * NMAX + d], 1);
        d_csr[b * EMAX + pos] = s;
    }
}

// ---------------------------------------------------------------------------
// Aggregation + concat:  cat[i, :512] = h[i] + sum_{j->i} h[j];  cat[i, 512:] = x[i]
// block per node, 128 threads, float4 lanes.
// ---------------------------------------------------------------------------
__global__ void __launch_bounds__(128) agg_cat_kernel(int n) {
    int b = blockIdx.y, i = blockIdx.x;
    if (i >= n) return;
    int t = threadIdx.x;
    size_t row = (size_t)(b * NMAX + i);

    float4 acc = ((const float4*)(d_hb + row * DIM))[t];
    int beg = d_off[b * (NMAX + 1) + i];
    int end = d_off[b * (NMAX + 1) + i + 1];
    for (int e = beg; e < end; e++) {
        int s = d_csr[b * EMAX + e];
        float4 v = ((const float4*)(d_hb + (size_t)(b * NMAX + s) * DIM))[t];
        acc.x += v.x; acc.y += v.y; acc.z += v.z; acc.w += v.w;
    }
    float4* cat = (float4*)(d_cat + row * 2 * DIM);
    cat[t] = acc;
    cat[128 + t] = ((const float4*)(d_xb + row * DIM))[t];
}

// ---------------------------------------------------------------------------
// Scores: score[i] = (x_new[i] . w) / ||w||   (x_new lives in d_hb)
// warp per node.
// ---------------------------------------------------------------------------
__global__ void score_kernel(const float* __restrict__ pw, int layer, int n) {
    int b    = blockIdx.y;
    int node = blockIdx.x * 8 + (threadIdx.x >> 5);
    int lane = threadIdx.x & 31;
    if (node >= n) return;
    const float* row = d_hb + (size_t)(b * NMAX + node) * DIM;
    const float* w   = pw + layer * DIM;
    float s = 0.f;
    for (int j = lane; j < DIM; j += 32) s = fmaf(row[j], w[j], s);
#pragma unroll
    for (int o = 16; o > 0; o >>= 1) s += __shfl_xor_sync(0xffffffffu, s, o);
    if (lane == 0) d_score[b * NMAX + node] = s * d_norms[layer];
}

// ---------------------------------------------------------------------------
// Top-k: one block per batch, bitonic sort 1024 (val, idx) pairs.
// Tie-break matches jax.lax.top_k: equal values -> lower index preferred.
// ---------------------------------------------------------------------------
__global__ void __launch_bounds__(512) topk_kernel(int n, int k) {
    __shared__ float sv[NMAX];
    __shared__ int   si[NMAX];
    int b = blockIdx.x, t = threadIdx.x;

    for (int i = t; i < NMAX; i += 512) {
        sv[i] = (i < n) ? d_score[b * NMAX + i] : -FLT_MAX;
        si[i] = i;
    }
    __syncthreads();

    for (int size = 2; size <= NMAX; size <<= 1) {
        for (int stride = size >> 1; stride > 0; stride >>= 1) {
            for (int i = t; i < NMAX; i += 512) {
                int j = i ^ stride;
                if (j > i) {
                    float v1 = sv[i], v2 = sv[j];
                    int   i1 = si[i], i2 = si[j];
                    // strict total order: "greater" = higher value, or equal value & lower idx
                    bool gt = (v1 > v2) || (v1 == v2 && i1 < i2);
                    bool up = ((i & size) == 0);          // ascending region
                    if (up ? gt : !gt) {
                        sv[i] = v2; sv[j] = v1;
                        si[i] = i2; si[j] = i1;
                    }
                }
            }
            __syncthreads();
        }
    }

    for (int i = t; i < NMAX; i += 512) d_newidx[b * NMAX + i] = -1;
    __syncthreads();
    for (int j = t; j < k; j += 512) {
        int   src = si[NMAX - 1 - j];
        float val = sv[NMAX - 1 - j];
        d_perm [b * NMAX + j]   = src;
        d_tanhv[b * NMAX + j]   = tanhf(val);
        d_newidx[b * NMAX + src] = j;
    }
}

// ---------------------------------------------------------------------------
// Gather pooled nodes: xb[j] = hb[perm[j]] * tanh(val[j])
// ---------------------------------------------------------------------------
__global__ void __launch_bounds__(128) gather_kernel(int k) {
    int b = blockIdx.y, j = blockIdx.x;
    if (j >= k) return;
    int t = threadIdx.x;
    int   p  = d_perm [b * NMAX + j];
    float tv = d_tanhv[b * NMAX + j];
    float4 v = ((const float4*)(d_hb + (size_t)(b * NMAX + p) * DIM))[t];
    ((float4*)(d_xb + (size_t)(b * NMAX + j) * DIM))[t] =
        make_float4(v.x * tv, v.y * tv, v.z * tv, v.w * tv);
}

// ---------------------------------------------------------------------------
// Remap edges into the pooled index space (-1 = dropped)
// ---------------------------------------------------------------------------
__global__ void remap_kernel(int inSel, int outSel) {
    int b = blockIdx.y;
    int e = blockIdx.x * blockDim.x + threadIdx.x;
    if (e >= EMAX) return;
    int s = esrc(inSel)[b * EMAX + e];
    int d = edst(inSel)[b * EMAX + e];
    int s2 = -1, d2 = 0;
    if (s >= 0) {
        s2 = d_newidx[b * NMAX + s];
        d2 = d_newidx[b * NMAX + d];
        if (d2 < 0) s2 = -1;
        if (d2 < 0) d2 = 0;
    }
    esrc_w(outSel)[b * EMAX + e] = s2;
    edst_w(outSel)[b * EMAX + e] = (s2 >= 0) ? d2 : 0;
}

// ---------------------------------------------------------------------------
// Readout: z[b, 0:512] (+)= max over k rows; z[b, 512:1024] (+)= mean
// ---------------------------------------------------------------------------
__global__ void readout_kernel(int k, int first) {
    int b = blockIdx.y;
    int f = blockIdx.x * 256 + threadIdx.x;   // grid.x = 2
    const float* base = d_xb + (size_t)b * NMAX * DIM + f;
    float mx = -FLT_MAX, sm = 0.f;
    for (int j = 0; j < k; j++) {
        float v = base[(size_t)j * DIM];
        mx = fmaxf(mx, v);
        sm += v;
    }
    float mean = sm / (float)k;
    if (first) {
        d_z[b * 2 * DIM + f]       = mx;
        d_z[b * 2 * DIM + DIM + f] = mean;
    } else {
        d_z[b * 2 * DIM + f]       += mx;
        d_z[b * 2 * DIM + DIM + f] += mean;
    }
}

// ---------------------------------------------------------------------------
// Final MLP: out = relu(z @ lin1^T + b1) @ lin2^T + b2
// one block per batch, 256 threads (8 warps).
// ---------------------------------------------------------------------------
__global__ void __launch_bounds__(256) mlp_kernel(
    const float* __restrict__ lin1W, const float* __restrict__ lin1b,
    const float* __restrict__ lin2W, const float* __restrict__ lin2b,
    float* __restrict__ out)
{
    int b = blockIdx.x, t = threadIdx.x;
    int warp = t >> 5, lane = t & 31;
    __shared__ float zsh[2 * DIM];
    __shared__ float y1[DIM];

    for (int i = t; i < 2 * DIM; i += 256) zsh[i] = d_z[b * 2 * DIM + i];
    __syncthreads();

    for (int o = warp * 64; o < warp * 64 + 64; o++) {
        const float* wr = lin1W + (size_t)o * 2 * DIM;
        float s = 0.f;
        for (int j = lane; j < 2 * DIM; j += 32) s = fmaf(zsh[j], wr[j], s);
#pragma unroll
        for (int off = 16; off > 0; off >>= 1) s += __shfl_xor_sync(0xffffffffu, s, off);
        if (lane == 0) y1[o] = fmaxf(s + lin1b[o], 0.f);
    }
    __syncthreads();

    for (int o = warp * 32; o < warp * 32 + 32; o++) {
        const float* wr = lin2W + (size_t)o * DIM;
        float s = 0.f;
        for (int j = lane; j < DIM; j += 32) s = fmaf(y1[j], wr[j], s);
#pragma unroll
        for (int off = 16; off > 0; off >>= 1) s += __shfl_xor_sync(0xffffffffu, s, off);
        if (lane == 0) out[b * 256 + o] = s + lin2b[o];
    }
}

// ---------------------------------------------------------------------------
// Host launcher
// ---------------------------------------------------------------------------
extern "C" void kernel_launch(void* const* d_in, const int* in_sizes, int n_in,
                              void* d_out, int out_size)
{
    const float* x       = (const float*)d_in[0];
    const int*   ei      = (const int*)  d_in[1];
    const float* c_lin_W = (const float*)d_in[2];
    const float* c_lin_b = (const float*)d_in[3];
    const float* c_upd_W = (const float*)d_in[4];
    const float* pool_w  = (const float*)d_in[5];
    const float* lin1_W  = (const float*)d_in[6];
    const float* lin1_b  = (const float*)d_in[7];
    const float* lin2_W  = (const float*)d_in[8];
    const float* lin2_b  = (const float*)d_in[9];
    float* out = (float*)d_out;

    const int ns[3] = {1024, 820, 656};
    const int ks[3] = {820, 656, 525};

    // init
    {
        size_t total = (size_t)BATCH * NMAX * DIM;
        copy_x_kernel<<<(unsigned)((total + 255) / 256), 256>>>(x);
        init_edges_kernel<<<dim3(EMAX / 256, BATCH), 256>>>(ei);
        norms_kernel<<<3, 256>>>(pool_w);
    }

    for (int l = 0; l < 3; l++) {
        int n = ns[l], k = ks[l];
        int inSel = l & 1;          // 0 -> A, 1 -> B
        int outSel = inSel ^ 1;

        // h = relu(x @ Wl^T + bl)
        gemm_nt_kernel<<<dim3(DIM / 128, (n + 127) / 128, BATCH), 256>>>(
            0, c_lin_W + (size_t)l * DIM * DIM, c_lin_b + l * DIM,
            n, DIM, DIM, 1);

        // CSR build on current edges
        zero_cnt_kernel<<<(BATCH * NMAX + 255) / 256, 256>>>();
        count_kernel<<<dim3(EMAX / 256, BATCH), 256>>>(inSel);
        scan_kernel<<<BATCH, 1024>>>(n);
        fill_kernel<<<dim3(EMAX / 256, BATCH), 256>>>(inSel);

        // cat = [h + neighbor-sum | x]
        agg_cat_kernel<<<dim3(n, BATCH), 128>>>(n);

        // x_new = relu(cat @ Wu^T)   -> d_hb
        gemm_nt_kernel<<<dim3(DIM / 128, (n + 127) / 128, BATCH), 256>>>(
            1, c_upd_W + (size_t)l * DIM * 2 * DIM, nullptr,
            n, DIM, 2 * DIM, 1);

        // top-k pooling
        score_kernel<<<dim3((n + 7) / 8, BATCH), 256>>>(pool_w, l, n);
        topk_kernel<<<BATCH, 512>>>(n, k);
        gather_kernel<<<dim3(k, BATCH), 128>>>(k);
        if (l < 2)
            remap_kernel<<<dim3(EMAX / 256, BATCH), 256>>>(inSel, outSel);

        // readout (max | mean) accumulated into z
        readout_kernel<<<dim3(DIM / 256, BATCH), 256>>>(k, l == 0 ? 1 : 0);
    }

    mlp_kernel<<<BATCH, 256>>>(lin1_W, lin1_b, lin2_W, lin2_b, out);
}

// round 3
// speedup vs baseline: 1.4985x; 1.4985x over previous
#include <cuda_runtime.h>
#include <cuda_bf16.h>
#include <cfloat>
#include <math.h>
#include <stdint.h>

// ---------------------------------------------------------------------------
// Problem constants (fixed by the reference)
// ---------------------------------------------------------------------------
#define BATCH 16
#define NMAX  1024
#define EMAX  16384
#define DIM   512
// ns = {1024, 820, 656}, ks = {820, 656, 525}

// ---------------------------------------------------------------------------
// Device scratch (static allocation; no cudaMalloc allowed)
// ---------------------------------------------------------------------------
__device__ float d_xb [BATCH * NMAX * DIM];        // pooled node features
__device__ float d_hb [BATCH * NMAX * DIM];        // h / x_new scratch
__device__ float d_cat[BATCH * NMAX * 2 * DIM];    // [agg | x] concat

__device__ int   d_srcA[BATCH * EMAX];
__device__ int   d_dstA[BATCH * EMAX];
__device__ int   d_srcB[BATCH * EMAX];
__device__ int   d_dstB[BATCH * EMAX];

__device__ int   d_off [BATCH * (NMAX + 1)];
__device__ int   d_csr [BATCH * EMAX];

__device__ float d_score[BATCH * NMAX];
__device__ int   d_perm [BATCH * NMAX];
__device__ float d_tanhv[BATCH * NMAX];
__device__ int   d_newidx[BATCH * NMAX];

__device__ float d_z[BATCH * 2 * DIM];
__device__ float d_norms[4];

__device__ __forceinline__ const int* esrc(int sel) { return sel ? d_srcB : d_srcA; }
__device__ __forceinline__ const int* edst(int sel) { return sel ? d_dstB : d_dstA; }
__device__ __forceinline__ int* esrc_w(int sel) { return sel ? d_srcB : d_srcA; }
__device__ __forceinline__ int* edst_w(int sel) { return sel ? d_dstB : d_dstA; }

// ---------------------------------------------------------------------------
// Small init kernels
// ---------------------------------------------------------------------------
__global__ void init_edges_kernel(const int* __restrict__ ei) {
    int b = blockIdx.y;
    int e = blockIdx.x * blockDim.x + threadIdx.x;
    if (e < EMAX) {
        d_srcA[b * EMAX + e] = ei[(size_t)b * 2 * EMAX + e];
        d_dstA[b * EMAX + e] = ei[(size_t)b * 2 * EMAX + EMAX + e];
    }
}

__global__ void norms_kernel(const float* __restrict__ pw) {
    int l = blockIdx.x;
    int t = threadIdx.x;  // 256
    __shared__ float red[256];
    float s = 0.f;
    for (int j = t; j < DIM; j += 256) {
        float v = pw[l * DIM + j];
        s = fmaf(v, v, s);
    }
    red[t] = s;
    __syncthreads();
    for (int o = 128; o > 0; o >>= 1) {
        if (t < o) red[t] += red[t + o];
        __syncthreads();
    }
    if (t == 0) d_norms[l] = 1.0f / sqrtf(red[0]);
}

// ---------------------------------------------------------------------------
// tf32 helpers
// ---------------------------------------------------------------------------
__device__ __forceinline__ uint32_t f2tf(float x) {
    uint32_t r;
    asm("cvt.rna.tf32.f32 %0, %1;" : "=r"(r) : "f"(x));
    return r;
}

__device__ __forceinline__ void mma_tf32(float* c, const uint32_t* a, const uint32_t* b) {
    asm volatile(
        "mma.sync.aligned.m16n8k8.row.col.f32.tf32.tf32.f32 "
        "{%0,%1,%2,%3}, {%4,%5,%6,%7}, {%8,%9}, {%0,%1,%2,%3};"
        : "+f"(c[0]), "+f"(c[1]), "+f"(c[2]), "+f"(c[3])
        : "r"(a[0]), "r"(a[1]), "r"(a[2]), "r"(a[3]), "r"(b[0]), "r"(b[1]));
}

__device__ __forceinline__ void cpasync16(uint32_t dst, const void* src, int szbytes) {
    asm volatile("cp.async.cg.shared.global [%0], [%1], 16, %2;"
                 :: "r"(dst), "l"(src), "r"(szbytes));
}
__device__ __forceinline__ void cpasync_commit() {
    asm volatile("cp.async.commit_group;");
}
template <int N>
__device__ __forceinline__ void cpasync_wait() {
    asm volatile("cp.async.wait_group %0;" :: "n"(N));
}

// ---------------------------------------------------------------------------
// 3xTF32 tensor-core GEMM
//   C[M,512] = act(A[M,K] @ W[512,K]^T + bias)
//   BM=128, BN=128, BK=16, 256 threads = 8 warps (2x4), warp tile 64x32.
//   asel: 0 -> A = xext (harness input), 1 -> A = d_xb, 2 -> A = d_cat.
//   All device-symbol resolution happens inside the kernel (no host API calls).
// ---------------------------------------------------------------------------
#define PITCH 20   // 16 + 4 pad: conflict-free fragment loads

__global__ void __launch_bounds__(256) gemm3t_kernel(
    int asel, const float* __restrict__ xext,
    const float* __restrict__ W,
    const float* __restrict__ bias,   // may be nullptr
    int M)
{
    __shared__ float As[2][128 * PITCH];
    __shared__ float Bs[2][128 * PITCH];

    const int b   = blockIdx.z;
    const int lda = (asel == 2) ? (2 * DIM) : DIM;
    const int K   = lda;
    const float* A =
        (asel == 0) ? (xext  + (size_t)b * NMAX * DIM) :
        (asel == 1) ? (d_xb  + (size_t)b * NMAX * DIM) :
                      (d_cat + (size_t)b * NMAX * 2 * DIM);
    float* C = d_hb + (size_t)b * NMAX * DIM;

    const int tid  = threadIdx.x;
    const int brow = blockIdx.y * 128;
    const int bcol = blockIdx.x * 128;

    const int warp = tid >> 5;
    const int lane = tid & 31;
    const int wm   = warp & 1;   // 0..1
    const int wn   = warp >> 1;  // 0..3
    const int quad = lane >> 2;  // 0..7
    const int tq   = lane & 3;   // 0..3

    // gmem->smem mapping: r = tid/2 (0..127), kq = (tid&1)*8, two float4 each
    const int lr = tid >> 1;
    const int kq = (tid & 1) * 8;
    int arow = brow + lr; if (arow >= M) arow = M - 1;
    const int avalid = (brow + lr) < M ? 16 : 0;
    const float* Aload = A + (size_t)arow * lda + kq;
    const float* Wload = W + (size_t)(bcol + lr) * K + kq;

    uint32_t sA0 = (uint32_t)__cvta_generic_to_shared(&As[0][lr * PITCH + kq]);
    uint32_t sA1 = (uint32_t)__cvta_generic_to_shared(&As[1][lr * PITCH + kq]);
    uint32_t sB0 = (uint32_t)__cvta_generic_to_shared(&Bs[0][lr * PITCH + kq]);
    uint32_t sB1 = (uint32_t)__cvta_generic_to_shared(&Bs[1][lr * PITCH + kq]);

    float acc[4][4][4];
#pragma unroll
    for (int i = 0; i < 4; i++)
#pragma unroll
        for (int j = 0; j < 4; j++)
#pragma unroll
            for (int e = 0; e < 4; e++) acc[i][j][e] = 0.f;

    const int nchunks = K >> 4;

    // prefetch chunk 0
    {
        cpasync16(sA0,      Aload,     avalid);
        cpasync16(sA0 + 16, Aload + 4, avalid);
        cpasync16(sB0,      Wload,     16);
        cpasync16(sB0 + 16, Wload + 4, 16);
        cpasync_commit();
    }

    for (int c = 0; c < nchunks; c++) {
        const int cur = c & 1;
        if (c + 1 < nchunks) {
            const int k0 = (c + 1) << 4;
            uint32_t dA = cur ? sA0 : sA1;
            uint32_t dB = cur ? sB0 : sB1;
            cpasync16(dA,      Aload + k0,     avalid);
            cpasync16(dA + 16, Aload + k0 + 4, avalid);
            cpasync16(dB,      Wload + k0,     16);
            cpasync16(dB + 16, Wload + k0 + 4, 16);
            cpasync_commit();
            cpasync_wait<1>();
        } else {
            cpasync_wait<0>();
        }
        __syncthreads();

        const float* as = As[cur];
        const float* bs = Bs[cur];

#pragma unroll
        for (int kk = 0; kk < 2; kk++) {
            const int kb = kk * 8;
            uint32_t ahi[4][4], alo[4][4];
#pragma unroll
            for (int mi = 0; mi < 4; mi++) {
                const int r0 = wm * 64 + mi * 16 + quad;
                float v0 = as[r0 * PITCH + kb + tq];
                float v1 = as[(r0 + 8) * PITCH + kb + tq];
                float v2 = as[r0 * PITCH + kb + tq + 4];
                float v3 = as[(r0 + 8) * PITCH + kb + tq + 4];
                ahi[mi][0] = f2tf(v0); alo[mi][0] = f2tf(v0 - __uint_as_float(ahi[mi][0]));
                ahi[mi][1] = f2tf(v1); alo[mi][1] = f2tf(v1 - __uint_as_float(ahi[mi][1]));
                ahi[mi][2] = f2tf(v2); alo[mi][2] = f2tf(v2 - __uint_as_float(ahi[mi][2]));
                ahi[mi][3] = f2tf(v3); alo[mi][3] = f2tf(v3 - __uint_as_float(ahi[mi][3]));
            }
            uint32_t bhi[4][2], blo[4][2];
#pragma unroll
            for (int ni = 0; ni < 4; ni++) {
                const int nr = wn * 32 + ni * 8 + quad;
                float u0 = bs[nr * PITCH + kb + tq];
                float u1 = bs[nr * PITCH + kb + tq + 4];
                bhi[ni][0] = f2tf(u0); blo[ni][0] = f2tf(u0 - __uint_as_float(bhi[ni][0]));
                bhi[ni][1] = f2tf(u1); blo[ni][1] = f2tf(u1 - __uint_as_float(bhi[ni][1]));
            }
#pragma unroll
            for (int mi = 0; mi < 4; mi++)
#pragma unroll
                for (int ni = 0; ni < 4; ni++) {
                    mma_tf32(acc[mi][ni], alo[mi], bhi[ni]);
                    mma_tf32(acc[mi][ni], ahi[mi], blo[ni]);
                    mma_tf32(acc[mi][ni], ahi[mi], bhi[ni]);
                }
        }
        __syncthreads();
    }

    // epilogue: bias + relu, float2 stores
#pragma unroll
    for (int mi = 0; mi < 4; mi++) {
        const int r0 = brow + wm * 64 + mi * 16 + quad;
#pragma unroll
        for (int ni = 0; ni < 4; ni++) {
            const int c0 = bcol + wn * 32 + ni * 8 + 2 * tq;
            float bv0 = 0.f, bv1 = 0.f;
            if (bias) { bv0 = bias[c0]; bv1 = bias[c0 + 1]; }
            if (r0 < M) {
                float2 v = make_float2(fmaxf(acc[mi][ni][0] + bv0, 0.f),
                                       fmaxf(acc[mi][ni][1] + bv1, 0.f));
                *(float2*)(C + (size_t)r0 * DIM + c0) = v;
            }
            if (r0 + 8 < M) {
                float2 v = make_float2(fmaxf(acc[mi][ni][2] + bv0, 0.f),
                                       fmaxf(acc[mi][ni][3] + bv1, 0.f));
                *(float2*)(C + (size_t)(r0 + 8) * DIM + c0) = v;
            }
        }
    }
}

// ---------------------------------------------------------------------------
// Fused CSR build: one block per batch (count + scan + fill, smem atomics)
// ---------------------------------------------------------------------------
__global__ void __launch_bounds__(1024) build_csr_kernel(int sel) {
    __shared__ int sh[NMAX];
    __shared__ int cur[NMAX];
    const int b = blockIdx.x, t = threadIdx.x;

    sh[t] = 0;
    __syncthreads();

    const int* S = esrc(sel) + b * EMAX;
    const int* D = edst(sel) + b * EMAX;

#pragma unroll 4
    for (int e = t; e < EMAX; e += 1024) {
        int s = S[e], d = D[e];
        if (s >= 0 && s != d) atomicAdd(&sh[d], 1);
    }
    __syncthreads();

    int v = sh[t];
    for (int off = 1; off < NMAX; off <<= 1) {
        int add = (t >= off) ? sh[t - off] : 0;
        __syncthreads();
        sh[t] += add;
        __syncthreads();
    }
    int excl = sh[t] - v;
    d_off[b * (NMAX + 1) + t] = excl;
    cur[t] = excl;
    if (t == NMAX - 1) d_off[b * (NMAX + 1) + NMAX] = sh[t];
    __syncthreads();

#pragma unroll 4
    for (int e = t; e < EMAX; e += 1024) {
        int s = S[e], d = D[e];
        if (s >= 0 && s != d) {
            int pos = atomicAdd(&cur[d], 1);
            d_csr[b * EMAX + pos] = s;
        }
    }
}

// ---------------------------------------------------------------------------
// Aggregation + concat: cat[i,:512] = h[i] + sum_{j->i} h[j]; cat[i,512:] = x[i]
// xsel: 0 -> x from harness input, 1 -> x = d_xb
// ---------------------------------------------------------------------------
__global__ void __launch_bounds__(128) agg_cat_kernel(int xsel, const float* __restrict__ xext, int n) {
    int b = blockIdx.y, i = blockIdx.x;
    if (i >= n) return;
    int t = threadIdx.x;
    size_t row = (size_t)(b * NMAX + i);
    const float* xsrc = xsel ? d_xb : xext;

    float4 acc = ((const float4*)(d_hb + row * DIM))[t];
    int beg = d_off[b * (NMAX + 1) + i];
    int end = d_off[b * (NMAX + 1) + i + 1];
    for (int e = beg; e < end; e++) {
        int s = d_csr[b * EMAX + e];
        float4 v = ((const float4*)(d_hb + (size_t)(b * NMAX + s) * DIM))[t];
        acc.x += v.x; acc.y += v.y; acc.z += v.z; acc.w += v.w;
    }
    float4* cat = (float4*)(d_cat + row * 2 * DIM);
    cat[t] = acc;
    cat[128 + t] = ((const float4*)(xsrc + row * DIM))[t];
}

// ---------------------------------------------------------------------------
// Scores: score[i] = (x_new[i] . w) / ||w||
// ---------------------------------------------------------------------------
__global__ void score_kernel(const float* __restrict__ pw, int layer, int n) {
    int b    = blockIdx.y;
    int node = blockIdx.x * 8 + (threadIdx.x >> 5);
    int lane = threadIdx.x & 31;
    if (node >= n) return;
    const float* row = d_hb + (size_t)(b * NMAX + node) * DIM;
    const float* w   = pw + layer * DIM;
    float s = 0.f;
#pragma unroll 4
    for (int j = lane; j < DIM; j += 32) s = fmaf(row[j], w[j], s);
#pragma unroll
    for (int o = 16; o > 0; o >>= 1) s += __shfl_xor_sync(0xffffffffu, s, o);
    if (lane == 0) d_score[b * NMAX + node] = s * d_norms[layer];
}

// ---------------------------------------------------------------------------
// Top-k via bitonic sort (tie-break: lower index wins, matching jax top_k)
// ---------------------------------------------------------------------------
__global__ void __launch_bounds__(512) topk_kernel(int n, int k) {
    __shared__ float sv[NMAX];
    __shared__ int   si[NMAX];
    int b = blockIdx.x, t = threadIdx.x;

    for (int i = t; i < NMAX; i += 512) {
        sv[i] = (i < n) ? d_score[b * NMAX + i] : -FLT_MAX;
        si[i] = i;
    }
    __syncthreads();

    for (int size = 2; size <= NMAX; size <<= 1) {
        for (int stride = size >> 1; stride > 0; stride >>= 1) {
            for (int i = t; i < NMAX; i += 512) {
                int j = i ^ stride;
                if (j > i) {
                    float v1 = sv[i], v2 = sv[j];
                    int   i1 = si[i], i2 = si[j];
                    bool gt = (v1 > v2) || (v1 == v2 && i1 < i2);
                    bool up = ((i & size) == 0);
                    if (up ? gt : !gt) {
                        sv[i] = v2; sv[j] = v1;
                        si[i] = i2; si[j] = i1;
                    }
                }
            }
            __syncthreads();
        }
    }

    for (int i = t; i < NMAX; i += 512) d_newidx[b * NMAX + i] = -1;
    __syncthreads();
    for (int j = t; j < k; j += 512) {
        int   src = si[NMAX - 1 - j];
        float val = sv[NMAX - 1 - j];
        d_perm [b * NMAX + j]    = src;
        d_tanhv[b * NMAX + j]    = tanhf(val);
        d_newidx[b * NMAX + src] = j;
    }
}

// ---------------------------------------------------------------------------
// Gather pooled nodes: xb[j] = hb[perm[j]] * tanh(val[j])
// ---------------------------------------------------------------------------
__global__ void __launch_bounds__(128) gather_kernel(int k) {
    int b = blockIdx.y, j = blockIdx.x;
    if (j >= k) return;
    int t = threadIdx.x;
    int   p  = d_perm [b * NMAX + j];
    float tv = d_tanhv[b * NMAX + j];
    float4 v = ((const float4*)(d_hb + (size_t)(b * NMAX + p) * DIM))[t];
    ((float4*)(d_xb + (size_t)(b * NMAX + j) * DIM))[t] =
        make_float4(v.x * tv, v.y * tv, v.z * tv, v.w * tv);
}

// ---------------------------------------------------------------------------
// Remap edges into pooled index space
// ---------------------------------------------------------------------------
__global__ void remap_kernel(int inSel, int outSel) {
    int b = blockIdx.y;
    int e = blockIdx.x * blockDim.x + threadIdx.x;
    if (e >= EMAX) return;
    int s = esrc(inSel)[b * EMAX + e];
    int d = edst(inSel)[b * EMAX + e];
    int s2 = -1, d2 = 0;
    if (s >= 0) {
        s2 = d_newidx[b * NMAX + s];
        d2 = d_newidx[b * NMAX + d];
        if (d2 < 0) s2 = -1;
        if (d2 < 0) d2 = 0;
    }
    esrc_w(outSel)[b * EMAX + e] = s2;
    edst_w(outSel)[b * EMAX + e] = (s2 >= 0) ? d2 : 0;
}

// ---------------------------------------------------------------------------
// Readout: z[b,0:512] (+)= max over k rows; z[b,512:1024] (+)= mean
// ---------------------------------------------------------------------------
__global__ void readout_kernel(int k, int first) {
    int b = blockIdx.y;
    int f = blockIdx.x * 256 + threadIdx.x;
    const float* base = d_xb + (size_t)b * NMAX * DIM + f;
    float mx = -FLT_MAX, sm = 0.f;
#pragma unroll 8
    for (int j = 0; j < k; j++) {
        float v = base[(size_t)j * DIM];
        mx = fmaxf(mx, v);
        sm += v;
    }
    float mean = sm / (float)k;
    if (first) {
        d_z[b * 2 * DIM + f]       = mx;
        d_z[b * 2 * DIM + DIM + f] = mean;
    } else {
        d_z[b * 2 * DIM + f]       += mx;
        d_z[b * 2 * DIM + DIM + f] += mean;
    }
}

// ---------------------------------------------------------------------------
// Final MLP: out = relu(z @ lin1^T + b1) @ lin2^T + b2
// ---------------------------------------------------------------------------
__global__ void __launch_bounds__(256) mlp_kernel(
    const float* __restrict__ lin1W, const float* __restrict__ lin1b,
    const float* __restrict__ lin2W, const float* __restrict__ lin2b,
    float* __restrict__ out)
{
    int b = blockIdx.x, t = threadIdx.x;
    int warp = t >> 5, lane = t & 31;
    __shared__ float zsh[2 * DIM];
    __shared__ float y1[DIM];

    for (int i = t; i < 2 * DIM; i += 256) zsh[i] = d_z[b * 2 * DIM + i];
    __syncthreads();

    for (int o = warp * 64; o < warp * 64 + 64; o++) {
        const float* wr = lin1W + (size_t)o * 2 * DIM;
        float s = 0.f;
        for (int j = lane; j < 2 * DIM; j += 32) s = fmaf(zsh[j], wr[j], s);
#pragma unroll
        for (int off = 16; off > 0; off >>= 1) s += __shfl_xor_sync(0xffffffffu, s, off);
        if (lane == 0) y1[o] = fmaxf(s + lin1b[o], 0.f);
    }
    __syncthreads();

    for (int o = warp * 32; o < warp * 32 + 32; o++) {
        const float* wr = lin2W + (size_t)o * DIM;
        float s = 0.f;
        for (int j = lane; j < DIM; j += 32) s = fmaf(y1[j], wr[j], s);
#pragma unroll
        for (int off = 16; off > 0; off >>= 1) s += __shfl_xor_sync(0xffffffffu, s, off);
        if (lane == 0) out[b * 256 + o] = s + lin2b[o];
    }
}

// ---------------------------------------------------------------------------
// Host launcher — kernel launches ONLY (graph-capture safe, no runtime API)
// ---------------------------------------------------------------------------
extern "C" void kernel_launch(void* const* d_in, const int* in_sizes, int n_in,
                              void* d_out, int out_size)
{
    const float* x       = (const float*)d_in[0];
    const int*   ei      = (const int*)  d_in[1];
    const float* c_lin_W = (const float*)d_in[2];
    const float* c_lin_b = (const float*)d_in[3];
    const float* c_upd_W = (const float*)d_in[4];
    const float* pool_w  = (const float*)d_in[5];
    const float* lin1_W  = (const float*)d_in[6];
    const float* lin1_b  = (const float*)d_in[7];
    const float* lin2_W  = (const float*)d_in[8];
    const float* lin2_b  = (const float*)d_in[9];
    float* out = (float*)d_out;

    const int ns[3] = {1024, 820, 656};
    const int ks[3] = {820, 656, 525};

    init_edges_kernel<<<dim3(EMAX / 256, BATCH), 256>>>(ei);
    norms_kernel<<<3, 256>>>(pool_w);

    for (int l = 0; l < 3; l++) {
        int n = ns[l], k = ks[l];
        int inSel = l & 1;
        int outSel = inSel ^ 1;
        int xsel = (l == 0) ? 0 : 1;

        // h = relu(x @ Wl^T + bl)
        gemm3t_kernel<<<dim3(DIM / 128, (n + 127) / 128, BATCH), 256>>>(
            xsel, x, c_lin_W + (size_t)l * DIM * DIM, c_lin_b + l * DIM, n);

        build_csr_kernel<<<BATCH, 1024>>>(inSel);

        agg_cat_kernel<<<dim3(n, BATCH), 128>>>(xsel, x, n);

        // x_new = relu(cat @ Wu^T)
        gemm3t_kernel<<<dim3(DIM / 128, (n + 127) / 128, BATCH), 256>>>(
            2, x, c_upd_W + (size_t)l * DIM * 2 * DIM, nullptr, n);

        score_kernel<<<dim3((n + 7) / 8, BATCH), 256>>>(pool_w, l, n);
        topk_kernel<<<BATCH, 512>>>(n, k);
        gather_kernel<<<dim3(k, BATCH), 128>>>(k);
        if (l < 2)
            remap_kernel<<<dim3(EMAX / 256, BATCH), 256>>>(inSel, outSel);

        readout_kernel<<<dim3(DIM / 256, BATCH), 256>>>(k, l == 0 ? 1 : 0);
    }

    mlp_kernel<<<BATCH, 256>>>(lin1_W, lin1_b, lin2_W, lin2_b, out);
}